// round 1
// baseline (speedup 1.0000x reference)
#include <cuda_runtime.h>
#include <cuda_bf16.h>
#include <math.h>

// Problem constants
#define B_   2
#define S_   2048
#define D_   1024
#define H_   16
#define HD_  64
#define R_   8
#define T_   2056      // S_ + R_
#define HALF_ 128
#define QKVW_ 3072     // 3*D_

// Scratch (device globals; no allocation allowed)
__device__ float g_xr[(size_t)B_ * T_ * D_];          // (B, T, D)
__device__ float g_qkv[(size_t)B_ * T_ * QKVW_];      // (B, T, 3*D)
__device__ float g_attn[(size_t)B_ * S_ * D_];        // (B, S, D) token rows only

// ---------------------------------------------------------------------------
// Kernel 1: build xr = concat(registers*(1+ada), x) along token dim
// ---------------------------------------------------------------------------
__global__ void build_xr_kernel(const float* __restrict__ x,
                                const float* __restrict__ ada,
                                const float* __restrict__ regs,
                                float* __restrict__ xr)
{
    int i = blockIdx.x * blockDim.x + threadIdx.x;   // over B*T*D/4
    const int D4 = D_ / 4;
    if (i >= B_ * T_ * D4) return;
    int d4 = i % D4;
    int t  = (i / D4) % T_;
    int b  = i / (T_ * D4);
    float4 v;
    if (t < R_) {
        float4 rv = ((const float4*)regs)[t * D4 + d4];
        float4 av = ((const float4*)ada)[b * D4 + d4];
        v = make_float4(rv.x * (1.f + av.x), rv.y * (1.f + av.y),
                        rv.z * (1.f + av.z), rv.w * (1.f + av.w));
    } else {
        v = ((const float4*)x)[((size_t)b * S_ + (t - R_)) * D4 + d4];
    }
    ((float4*)xr)[i] = v;
}

// ---------------------------------------------------------------------------
// Kernel 2: C[M,N] = A[M,K] @ W[N,K]^T + bias[N]   (both A and W K-major)
// 128x128 tile, BK=8, 8x8 per thread, 256 threads.
// N, K must be multiples of 128 / 8 (they are); M guarded.
// ---------------------------------------------------------------------------
__global__ __launch_bounds__(256)
void sgemm_nt_bias(const float* __restrict__ A, const float* __restrict__ W,
                   const float* __restrict__ bias, float* __restrict__ C,
                   int M, int N, int K)
{
    __shared__ float As[8][128];
    __shared__ float Bs[8][128];

    const int tid  = threadIdx.x;
    const int brow = blockIdx.y * 128;
    const int bcol = blockIdx.x * 128;

    const int loadRow = tid >> 1;          // 0..127
    const int loadCol = (tid & 1) << 2;    // 0 or 4
    const int tx = (tid & 15) << 3;        // col offset 0..120
    const int ty = (tid >> 4) << 3;        // row offset 0..120

    float acc[8][8];
#pragma unroll
    for (int i = 0; i < 8; i++)
#pragma unroll
        for (int j = 0; j < 8; j++) acc[i][j] = 0.f;

    const bool aValid = (brow + loadRow) < M;
    const float* aPtr = A + (size_t)(brow + loadRow) * K + loadCol;
    const float* wPtr = W + (size_t)(bcol + loadRow) * K + loadCol;

    for (int k0 = 0; k0 < K; k0 += 8) {
        float4 av = aValid ? *(const float4*)(aPtr + k0) : make_float4(0.f, 0.f, 0.f, 0.f);
        float4 wv = *(const float4*)(wPtr + k0);
        __syncthreads();
        As[loadCol + 0][loadRow] = av.x;
        As[loadCol + 1][loadRow] = av.y;
        As[loadCol + 2][loadRow] = av.z;
        As[loadCol + 3][loadRow] = av.w;
        Bs[loadCol + 0][loadRow] = wv.x;
        Bs[loadCol + 1][loadRow] = wv.y;
        Bs[loadCol + 2][loadRow] = wv.z;
        Bs[loadCol + 3][loadRow] = wv.w;
        __syncthreads();
#pragma unroll
        for (int kk = 0; kk < 8; kk++) {
            float ra[8], rb[8];
            *(float4*)&ra[0] = *(const float4*)&As[kk][ty];
            *(float4*)&ra[4] = *(const float4*)&As[kk][ty + 4];
            *(float4*)&rb[0] = *(const float4*)&Bs[kk][tx];
            *(float4*)&rb[4] = *(const float4*)&Bs[kk][tx + 4];
#pragma unroll
            for (int i = 0; i < 8; i++)
#pragma unroll
                for (int j = 0; j < 8; j++)
                    acc[i][j] += ra[i] * rb[j];
        }
    }

#pragma unroll
    for (int i = 0; i < 8; i++) {
        int row = brow + ty + i;
        if (row < M) {
#pragma unroll
            for (int j = 0; j < 8; j += 4) {
                int col = bcol + tx + j;
                float4 bv = *(const float4*)(bias + col);
                float4 cv = make_float4(acc[i][j] + bv.x, acc[i][j + 1] + bv.y,
                                        acc[i][j + 2] + bv.z, acc[i][j + 3] + bv.w);
                *(float4*)(C + (size_t)row * N + col) = cv;
            }
        }
    }
}

// ---------------------------------------------------------------------------
// Kernel 3: sliding-window attention, token queries only.
// grid (S/64, H, B), 256 threads = 8 warps; warp owns 8 queries.
// Keys: chunk 0 = 8 registers (always attended), then 64-key token chunks
// covering [qb-128, qb+192) clamped (always 64-aligned).
// Online softmax; lane l owns output dims l and l+32.
// ---------------------------------------------------------------------------
__global__ __launch_bounds__(256)
void attn_kernel(const float* __restrict__ qkv, float* __restrict__ out)
{
    __shared__ float Ks[64][64];
    __shared__ float Vs[64][64];

    const int b = blockIdx.z, h = blockIdx.y, qt = blockIdx.x;
    const int warp = threadIdx.x >> 5, lane = threadIdx.x & 31;
    const float* base = qkv + (size_t)b * T_ * QKVW_;
    const int qb = qt * 64;

    float qv0[8], qv1[8], acc0[8], acc1[8], mval[8], lsum[8];
#pragma unroll
    for (int qi = 0; qi < 8; qi++) {
        int qtok = qb + warp * 8 + qi;
        const float* qp = base + (size_t)(R_ + qtok) * QKVW_ + h * HD_;
        qv0[qi] = qp[lane];
        qv1[qi] = qp[lane + 32];
        acc0[qi] = 0.f; acc1[qi] = 0.f;
        mval[qi] = -1e30f; lsum[qi] = 0.f;
    }

    const int kstart = max(0, qb - HALF_);
    const int kend   = min(S_, qb + 64 + HALF_);
    const int nchunks = (kend - kstart) >> 6;     // token chunks (each exactly 64)

    for (int c = 0; c <= nchunks; c++) {
        const int nk   = (c == 0) ? R_ : 64;
        const int krow = (c == 0) ? 0 : (R_ + kstart + (c - 1) * 64);
        __syncthreads();
        for (int i = threadIdx.x; i < nk * 16; i += 256) {
            int j = i >> 4, seg = (i & 15) << 2;
            const float* kp = base + (size_t)(krow + j) * QKVW_ + D_ + h * HD_ + seg;
            *(float4*)&Ks[j][seg] = *(const float4*)kp;
            *(float4*)&Vs[j][seg] = *(const float4*)(kp + D_);
        }
        __syncthreads();

        const bool isReg = (c == 0);
        const int ktok0  = isReg ? 0 : (kstart + (c - 1) * 64);

        for (int j = 0; j < nk; j++) {
            float k0 = Ks[j][lane], k1 = Ks[j][lane + 32];
            float v0 = Vs[j][lane], v1 = Vs[j][lane + 32];
            int ktok = ktok0 + j;
#pragma unroll
            for (int qi = 0; qi < 8; qi++) {
                float s = qv0[qi] * k0 + qv1[qi] * k1;
                s += __shfl_xor_sync(0xffffffffu, s, 16);
                s += __shfl_xor_sync(0xffffffffu, s, 8);
                s += __shfl_xor_sync(0xffffffffu, s, 4);
                s += __shfl_xor_sync(0xffffffffu, s, 2);
                s += __shfl_xor_sync(0xffffffffu, s, 1);
                s *= 0.125f;                           // 1/sqrt(64)
                int qtok = qb + warp * 8 + qi;
                if (isReg || abs(ktok - qtok) <= HALF_) {
                    float mn   = fmaxf(mval[qi], s);
                    float corr = __expf(mval[qi] - mn);
                    float p    = __expf(s - mn);
                    lsum[qi] = lsum[qi] * corr + p;
                    acc0[qi] = acc0[qi] * corr + p * v0;
                    acc1[qi] = acc1[qi] * corr + p * v1;
                    mval[qi] = mn;
                }
            }
        }
    }

#pragma unroll
    for (int qi = 0; qi < 8; qi++) {
        int qtok = qb + warp * 8 + qi;
        float inv = 1.0f / lsum[qi];
        float* op = out + ((size_t)b * S_ + qtok) * D_ + h * HD_;
        op[lane]      = acc0[qi] * inv;
        op[lane + 32] = acc1[qi] * inv;
    }
}

// ---------------------------------------------------------------------------
// Launch
// ---------------------------------------------------------------------------
extern "C" void kernel_launch(void* const* d_in, const int* in_sizes, int n_in,
                              void* d_out, int out_size)
{
    const float* x      = (const float*)d_in[0];
    const float* ada    = (const float*)d_in[1];
    const float* regs   = (const float*)d_in[2];
    const float* W_qkv  = (const float*)d_in[3];
    const float* b_qkv  = (const float*)d_in[4];
    const float* W_out  = (const float*)d_in[5];
    const float* b_out  = (const float*)d_in[6];
    float* out = (float*)d_out;

    float *xr, *qkvbuf, *attn;
    cudaGetSymbolAddress((void**)&xr,    g_xr);
    cudaGetSymbolAddress((void**)&qkvbuf, g_qkv);
    cudaGetSymbolAddress((void**)&attn,  g_attn);

    // 1. build xr
    const int n4 = B_ * T_ * (D_ / 4);
    build_xr_kernel<<<(n4 + 255) / 256, 256>>>(x, ada, regs, xr);

    // 2. qkv = xr @ W_qkv^T + b_qkv  : M=4112, N=3072, K=1024
    sgemm_nt_bias<<<dim3(QKVW_ / 128, (B_ * T_ + 127) / 128), 256>>>(
        xr, W_qkv, b_qkv, qkvbuf, B_ * T_, QKVW_, D_);

    // 3. windowed attention (token queries only)
    attn_kernel<<<dim3(S_ / 64, H_, B_), 256>>>(qkvbuf, attn);

    // 4. out = attn @ W_out^T + b_out : M = B*S = 4096 (rows are contiguous)
    sgemm_nt_bias<<<dim3(D_ / 128, (B_ * S_) / 128), 256>>>(
        attn, W_out, b_out, out, B_ * S_, D_, D_);
}

// round 2
// speedup vs baseline: 1.6304x; 1.6304x over previous
#include <cuda_runtime.h>
#include <cuda_bf16.h>
#include <math.h>

// Problem constants
#define B_   2
#define S_   2048
#define D_   1024
#define H_   16
#define HD_  64
#define R_   8
#define T_   2056      // S_ + R_
#define HALF_ 128
#define QKVW_ 3072     // 3*D_

// Scratch (device globals; no allocation allowed)
__device__ float g_xr[(size_t)B_ * T_ * D_];          // (B, T, D)
__device__ float g_qkv[(size_t)B_ * T_ * QKVW_];      // (B, T, 3*D)
__device__ float g_attn[(size_t)B_ * S_ * D_];        // (B, S, D) token rows only

// ---------------------------------------------------------------------------
// Kernel 1: build xr = concat(registers*(1+ada), x) along token dim
// ---------------------------------------------------------------------------
__global__ void build_xr_kernel(const float* __restrict__ x,
                                const float* __restrict__ ada,
                                const float* __restrict__ regs,
                                float* __restrict__ xr)
{
    int i = blockIdx.x * blockDim.x + threadIdx.x;   // over B*T*D/4
    const int D4 = D_ / 4;
    if (i >= B_ * T_ * D4) return;
    int d4 = i % D4;
    int t  = (i / D4) % T_;
    int b  = i / (T_ * D4);
    float4 v;
    if (t < R_) {
        float4 rv = ((const float4*)regs)[t * D4 + d4];
        float4 av = ((const float4*)ada)[b * D4 + d4];
        v = make_float4(rv.x * (1.f + av.x), rv.y * (1.f + av.y),
                        rv.z * (1.f + av.z), rv.w * (1.f + av.w));
    } else {
        v = ((const float4*)x)[((size_t)b * S_ + (t - R_)) * D4 + d4];
    }
    ((float4*)xr)[i] = v;
}

// ---------------------------------------------------------------------------
// Kernel 2: C[M,N] = A[M,K] @ W[N,K]^T + bias[N], double-buffered smem.
// 128x128 tile, BK=8, 8x8 per thread, 256 threads, one sync per K-step.
// ---------------------------------------------------------------------------
__global__ __launch_bounds__(256)
void sgemm_nt_bias(const float* __restrict__ A, const float* __restrict__ W,
                   const float* __restrict__ bias, float* __restrict__ C,
                   int M, int N, int K)
{
    __shared__ float As[2][8][128];
    __shared__ float Bs[2][8][128];

    const int tid  = threadIdx.x;
    const int brow = blockIdx.y * 128;
    const int bcol = blockIdx.x * 128;

    const int loadRow = tid >> 1;          // 0..127
    const int loadCol = (tid & 1) << 2;    // 0 or 4
    const int tx = (tid & 15) << 3;        // col offset 0..120
    const int ty = (tid >> 4) << 3;        // row offset 0..120

    float acc[8][8];
#pragma unroll
    for (int i = 0; i < 8; i++)
#pragma unroll
        for (int j = 0; j < 8; j++) acc[i][j] = 0.f;

    const bool aValid = (brow + loadRow) < M;
    const float* aPtr = A + (size_t)(brow + loadRow) * K + loadCol;
    const float* wPtr = W + (size_t)(bcol + loadRow) * K + loadCol;

    // prologue: load tile 0 into buffer 0
    {
        float4 av = aValid ? *(const float4*)(aPtr) : make_float4(0.f, 0.f, 0.f, 0.f);
        float4 wv = *(const float4*)(wPtr);
        As[0][loadCol + 0][loadRow] = av.x;
        As[0][loadCol + 1][loadRow] = av.y;
        As[0][loadCol + 2][loadRow] = av.z;
        As[0][loadCol + 3][loadRow] = av.w;
        Bs[0][loadCol + 0][loadRow] = wv.x;
        Bs[0][loadCol + 1][loadRow] = wv.y;
        Bs[0][loadCol + 2][loadRow] = wv.z;
        Bs[0][loadCol + 3][loadRow] = wv.w;
    }
    __syncthreads();

    const int nT = K >> 3;
    for (int t = 0; t < nT; t++) {
        const int cur = t & 1;
        float4 av2, wv2;
        const bool more = (t + 1) < nT;
        if (more) {
            av2 = aValid ? *(const float4*)(aPtr + (t + 1) * 8)
                         : make_float4(0.f, 0.f, 0.f, 0.f);
            wv2 = *(const float4*)(wPtr + (t + 1) * 8);
        }
#pragma unroll
        for (int kk = 0; kk < 8; kk++) {
            float ra[8], rb[8];
            *(float4*)&ra[0] = *(const float4*)&As[cur][kk][ty];
            *(float4*)&ra[4] = *(const float4*)&As[cur][kk][ty + 4];
            *(float4*)&rb[0] = *(const float4*)&Bs[cur][kk][tx];
            *(float4*)&rb[4] = *(const float4*)&Bs[cur][kk][tx + 4];
#pragma unroll
            for (int i = 0; i < 8; i++)
#pragma unroll
                for (int j = 0; j < 8; j++)
                    acc[i][j] += ra[i] * rb[j];
        }
        if (more) {
            const int nxt = cur ^ 1;
            As[nxt][loadCol + 0][loadRow] = av2.x;
            As[nxt][loadCol + 1][loadRow] = av2.y;
            As[nxt][loadCol + 2][loadRow] = av2.z;
            As[nxt][loadCol + 3][loadRow] = av2.w;
            Bs[nxt][loadCol + 0][loadRow] = wv2.x;
            Bs[nxt][loadCol + 1][loadRow] = wv2.y;
            Bs[nxt][loadCol + 2][loadRow] = wv2.z;
            Bs[nxt][loadCol + 3][loadRow] = wv2.w;
            __syncthreads();
        }
    }

#pragma unroll
    for (int i = 0; i < 8; i++) {
        int row = brow + ty + i;
        if (row < M) {
#pragma unroll
            for (int j = 0; j < 8; j += 4) {
                int col = bcol + tx + j;
                float4 bv = *(const float4*)(bias + col);
                float4 cv = make_float4(acc[i][j] + bv.x, acc[i][j + 1] + bv.y,
                                        acc[i][j + 2] + bv.z, acc[i][j + 3] + bv.w);
                *(float4*)(C + (size_t)row * N + col) = cv;
            }
        }
    }
}

// ---------------------------------------------------------------------------
// Kernel 3: flash-style sliding-window attention, token queries only.
// grid (S/64, H, B), 256 threads laid out 16x16; thread (ty,tx) owns a 4x4
// tile: queries q0..q0+3, keys/dims k0..k0+3. Key stream = [8 registers,
// window tokens], consumed in 64-key chunks. P overwrites the K smem buffer
// so total static smem = 48KB exactly.
// ---------------------------------------------------------------------------
__global__ __launch_bounds__(256)
void attn_kernel(const float* __restrict__ qkv, float* __restrict__ out)
{
    __shared__ float Qt[64][64];   // [d][q]  (Q transposed)
    __shared__ float KP[64][64];   // phase 1: K transposed [d][k]; phase 2: P [k][q]
    __shared__ float Vs[64][64];   // [k][d]  (natural)

    const int b  = blockIdx.z, h = blockIdx.y;
    const int qb = blockIdx.x * 64;
    const int tid = threadIdx.x;
    const int tx = tid & 15, ty = tid >> 4;
    const int q0 = ty * 4, k0 = tx * 4;    // k0 doubles as d0 in PV/output

    const float* base = qkv + (size_t)b * T_ * QKVW_;

    // Load Q tile transposed
    for (int i = tid; i < 64 * 16; i += 256) {
        int q = i >> 4, seg = (i & 15) << 2;
        const float* qp = base + (size_t)(R_ + qb + q) * QKVW_ + h * HD_ + seg;
        float4 v = *(const float4*)qp;
        Qt[seg + 0][q] = v.x; Qt[seg + 1][q] = v.y;
        Qt[seg + 2][q] = v.z; Qt[seg + 3][q] = v.w;
    }

    float oacc[4][4];
    float m[4], l[4];
#pragma unroll
    for (int i = 0; i < 4; i++) {
        m[i] = -1e30f; l[i] = 0.f;
#pragma unroll
        for (int j = 0; j < 4; j++) oacc[i][j] = 0.f;
    }

    const int kstart = max(0, qb - HALF_);
    const int kend   = min(S_, qb + 64 + HALF_);
    const int nkeys  = R_ + (kend - kstart);
    const int nchunks = (nkeys + 63) >> 6;

    for (int c = 0; c < nchunks; c++) {
        __syncthreads();   // previous chunk's PV reads of KP/Vs must finish
        // Load K (transposed) and V chunk
        for (int i = tid; i < 64 * 16; i += 256) {
            int j = i >> 4, seg = (i & 15) << 2;
            int g = c * 64 + j;
            int row = (g < R_) ? g : (R_ + kstart + g - R_);
            if (g >= nkeys) row = 0;   // dummy; masked below
            const float* kp = base + (size_t)row * QKVW_ + D_ + h * HD_ + seg;
            float4 kv = *(const float4*)kp;
            KP[seg + 0][j] = kv.x; KP[seg + 1][j] = kv.y;
            KP[seg + 2][j] = kv.z; KP[seg + 3][j] = kv.w;
            *(float4*)&Vs[j][seg] = *(const float4*)(kp + D_);
        }
        __syncthreads();

        // S = Q K^T (4x4 register tile)
        float s[4][4];
#pragma unroll
        for (int i = 0; i < 4; i++)
#pragma unroll
            for (int j = 0; j < 4; j++) s[i][j] = 0.f;
#pragma unroll 8
        for (int kk = 0; kk < 64; kk++) {
            float4 qa = *(const float4*)&Qt[kk][q0];
            float4 kb = *(const float4*)&KP[kk][k0];
            float ra[4] = {qa.x, qa.y, qa.z, qa.w};
            float rb[4] = {kb.x, kb.y, kb.z, kb.w};
#pragma unroll
            for (int i = 0; i < 4; i++)
#pragma unroll
                for (int j = 0; j < 4; j++)
                    s[i][j] += ra[i] * rb[j];
        }

        // scale + mask
#pragma unroll
        for (int j = 0; j < 4; j++) {
            int g = c * 64 + k0 + j;
            int ktok = kstart + g - R_;
            bool isreg = g < R_;
            bool inb   = g < nkeys;
#pragma unroll
            for (int i = 0; i < 4; i++) {
                int qtok = qb + q0 + i;
                bool valid = inb && (isreg ||
                             (ktok >= qtok - HALF_ && ktok <= qtok + HALF_));
                s[i][j] = valid ? s[i][j] * 0.125f : -1e30f;
            }
        }

        // online softmax update (rows reduced across 16 lanes of half-warp)
#pragma unroll
        for (int i = 0; i < 4; i++) {
            float cm = fmaxf(fmaxf(s[i][0], s[i][1]), fmaxf(s[i][2], s[i][3]));
            cm = fmaxf(cm, __shfl_xor_sync(0xffffffffu, cm, 1));
            cm = fmaxf(cm, __shfl_xor_sync(0xffffffffu, cm, 2));
            cm = fmaxf(cm, __shfl_xor_sync(0xffffffffu, cm, 4));
            cm = fmaxf(cm, __shfl_xor_sync(0xffffffffu, cm, 8));
            float mn = fmaxf(m[i], cm);
            float corr = __expf(m[i] - mn);
            float ps = 0.f;
#pragma unroll
            for (int j = 0; j < 4; j++) {
                s[i][j] = __expf(s[i][j] - mn);
                ps += s[i][j];
            }
            ps += __shfl_xor_sync(0xffffffffu, ps, 1);
            ps += __shfl_xor_sync(0xffffffffu, ps, 2);
            ps += __shfl_xor_sync(0xffffffffu, ps, 4);
            ps += __shfl_xor_sync(0xffffffffu, ps, 8);
            l[i] = l[i] * corr + ps;
#pragma unroll
            for (int j = 0; j < 4; j++) oacc[i][j] *= corr;
            m[i] = mn;
        }

        __syncthreads();   // all K reads done -> safe to overwrite KP with P
        // write P transposed: P[k][q]
#pragma unroll
        for (int j = 0; j < 4; j++) {
            float4 pv = make_float4(s[0][j], s[1][j], s[2][j], s[3][j]);
            *(float4*)&KP[k0 + j][q0] = pv;
        }
        __syncthreads();

        // O += P V (4x4 register tile; k0 = output dim offset)
#pragma unroll 8
        for (int kk = 0; kk < 64; kk++) {
            float4 pa = *(const float4*)&KP[kk][q0];
            float4 vb = *(const float4*)&Vs[kk][k0];
            float ra[4] = {pa.x, pa.y, pa.z, pa.w};
            float rb[4] = {vb.x, vb.y, vb.z, vb.w};
#pragma unroll
            for (int i = 0; i < 4; i++)
#pragma unroll
                for (int j = 0; j < 4; j++)
                    oacc[i][j] += ra[i] * rb[j];
        }
    }

    // write normalized output
#pragma unroll
    for (int i = 0; i < 4; i++) {
        float inv = 1.0f / l[i];
        float4 o = make_float4(oacc[i][0] * inv, oacc[i][1] * inv,
                               oacc[i][2] * inv, oacc[i][3] * inv);
        *(float4*)(out + ((size_t)b * S_ + qb + q0 + i) * D_ + h * HD_ + k0) = o;
    }
}

// ---------------------------------------------------------------------------
// Launch
// ---------------------------------------------------------------------------
extern "C" void kernel_launch(void* const* d_in, const int* in_sizes, int n_in,
                              void* d_out, int out_size)
{
    const float* x      = (const float*)d_in[0];
    const float* ada    = (const float*)d_in[1];
    const float* regs   = (const float*)d_in[2];
    const float* W_qkv  = (const float*)d_in[3];
    const float* b_qkv  = (const float*)d_in[4];
    const float* W_out  = (const float*)d_in[5];
    const float* b_out  = (const float*)d_in[6];
    float* out = (float*)d_out;

    float *xr, *qkvbuf, *attn;
    cudaGetSymbolAddress((void**)&xr,    g_xr);
    cudaGetSymbolAddress((void**)&qkvbuf, g_qkv);
    cudaGetSymbolAddress((void**)&attn,  g_attn);

    // 1. build xr
    const int n4 = B_ * T_ * (D_ / 4);
    build_xr_kernel<<<(n4 + 255) / 256, 256>>>(x, ada, regs, xr);

    // 2. qkv = xr @ W_qkv^T + b_qkv  : M=4112, N=3072, K=1024
    sgemm_nt_bias<<<dim3(QKVW_ / 128, (B_ * T_ + 127) / 128), 256>>>(
        xr, W_qkv, b_qkv, qkvbuf, B_ * T_, QKVW_, D_);

    // 3. windowed attention (token queries only)
    attn_kernel<<<dim3(S_ / 64, H_, B_), 256>>>(qkvbuf, attn);

    // 4. out = attn @ W_out^T + b_out : M = B*S = 4096 (rows are contiguous)
    sgemm_nt_bias<<<dim3(D_ / 128, (B_ * S_) / 128), 256>>>(
        attn, W_out, b_out, out, B_ * S_, D_, D_);
}

// round 4
// speedup vs baseline: 3.5657x; 2.1870x over previous
#include <cuda_runtime.h>
#include <cuda_bf16.h>
#include <math.h>
#include <stdint.h>

// Problem constants
#define B_   2
#define S_   2048
#define D_   1024
#define H_   16
#define HD_  64
#define R_   8
#define T_   2056      // S_ + R_
#define HALF_ 128
#define QKVW_ 3072     // 3*D_

// Scratch (device globals; no allocation allowed)
__device__ __align__(16) __nv_bfloat16 g_xr_hi[(size_t)B_ * T_ * D_];
__device__ __align__(16) __nv_bfloat16 g_xr_lo[(size_t)B_ * T_ * D_];
__device__ __align__(16) __nv_bfloat16 g_wq_hi[(size_t)QKVW_ * D_];
__device__ __align__(16) __nv_bfloat16 g_wq_lo[(size_t)QKVW_ * D_];
__device__ __align__(16) __nv_bfloat16 g_wo_hi[(size_t)D_ * D_];
__device__ __align__(16) __nv_bfloat16 g_wo_lo[(size_t)D_ * D_];
__device__ __align__(16) __nv_bfloat16 g_at_hi[(size_t)B_ * S_ * D_];
__device__ __align__(16) __nv_bfloat16 g_at_lo[(size_t)B_ * S_ * D_];
__device__ __align__(16) float g_qkv[(size_t)B_ * T_ * QKVW_];

// ---------------------------------------------------------------------------
// helpers
// ---------------------------------------------------------------------------
__device__ __forceinline__ uint32_t smem_u32(const void* p) {
    uint32_t a;
    asm("{ .reg .u64 t; cvta.to.shared.u64 t, %1; cvt.u32.u64 %0, t; }"
        : "=r"(a) : "l"(p));
    return a;
}
__device__ __forceinline__ uint32_t sw128(uint32_t off) {
    return off ^ ((off >> 3) & 0x70);
}
__device__ __forceinline__ void cp16(uint32_t dst, const void* src) {
    asm volatile("cp.async.cg.shared.global [%0], [%1], 16;"
                 :: "r"(dst), "l"(src) : "memory");
}
__device__ __forceinline__ void cp_commit() {
    asm volatile("cp.async.commit_group;" ::: "memory");
}
__device__ __forceinline__ void cp_wait0() {
    asm volatile("cp.async.wait_group 0;" ::: "memory");
}
__device__ __forceinline__ void ldm_x4(uint32_t* r, uint32_t addr) {
    asm volatile("ldmatrix.sync.aligned.m8n8.x4.shared.b16 {%0,%1,%2,%3}, [%4];"
                 : "=r"(r[0]), "=r"(r[1]), "=r"(r[2]), "=r"(r[3]) : "r"(addr));
}
__device__ __forceinline__ void mma16816(float* c, const uint32_t* a, const uint32_t* b) {
    asm volatile(
        "mma.sync.aligned.m16n8k16.row.col.f32.bf16.bf16.f32 "
        "{%0,%1,%2,%3}, {%4,%5,%6,%7}, {%8,%9}, {%0,%1,%2,%3};"
        : "+f"(c[0]), "+f"(c[1]), "+f"(c[2]), "+f"(c[3])
        : "r"(a[0]), "r"(a[1]), "r"(a[2]), "r"(a[3]), "r"(b[0]), "r"(b[1]));
}

// pack 4 floats -> hi bf16x4 (uint2) and lo bf16x4 (uint2)
__device__ __forceinline__ void split4(float4 v, uint2& hi, uint2& lo) {
    __nv_bfloat16 h0 = __float2bfloat16_rn(v.x);
    __nv_bfloat16 h1 = __float2bfloat16_rn(v.y);
    __nv_bfloat16 h2 = __float2bfloat16_rn(v.z);
    __nv_bfloat16 h3 = __float2bfloat16_rn(v.w);
    hi.x = ((uint32_t)__bfloat16_as_ushort(h1) << 16) | __bfloat16_as_ushort(h0);
    hi.y = ((uint32_t)__bfloat16_as_ushort(h3) << 16) | __bfloat16_as_ushort(h2);
    __nv_bfloat162 l01 = __floats2bfloat162_rn(v.x - __bfloat162float(h0),
                                               v.y - __bfloat162float(h1));
    __nv_bfloat162 l23 = __floats2bfloat162_rn(v.z - __bfloat162float(h2),
                                               v.w - __bfloat162float(h3));
    lo.x = *(uint32_t*)&l01;
    lo.y = *(uint32_t*)&l23;
}

// ---------------------------------------------------------------------------
// Kernel 1: build xr (hi/lo planes) = concat(registers*(1+ada), x)
// ---------------------------------------------------------------------------
__global__ void build_xr_split(const float* __restrict__ x,
                               const float* __restrict__ ada,
                               const float* __restrict__ regs,
                               __nv_bfloat16* __restrict__ xh,
                               __nv_bfloat16* __restrict__ xl)
{
    int i = blockIdx.x * blockDim.x + threadIdx.x;
    const int D4 = D_ / 4;
    if (i >= B_ * T_ * D4) return;
    int d4 = i % D4;
    int t  = (i / D4) % T_;
    int b  = i / (T_ * D4);
    float4 v;
    if (t < R_) {
        float4 rv = ((const float4*)regs)[t * D4 + d4];
        float4 av = ((const float4*)ada)[b * D4 + d4];
        v = make_float4(rv.x * (1.f + av.x), rv.y * (1.f + av.y),
                        rv.z * (1.f + av.z), rv.w * (1.f + av.w));
    } else {
        v = ((const float4*)x)[((size_t)b * S_ + (t - R_)) * D4 + d4];
    }
    uint2 hi, lo;
    split4(v, hi, lo);
    ((uint2*)xh)[i] = hi;
    ((uint2*)xl)[i] = lo;
}

// ---------------------------------------------------------------------------
// Kernel: generic fp32 -> (hi, lo) bf16 split
// ---------------------------------------------------------------------------
__global__ void split_planes(const float* __restrict__ src,
                             __nv_bfloat16* __restrict__ hi,
                             __nv_bfloat16* __restrict__ lo, int n4)
{
    int i = blockIdx.x * blockDim.x + threadIdx.x;
    if (i >= n4) return;
    float4 v = ((const float4*)src)[i];
    uint2 h, l;
    split4(v, h, l);
    ((uint2*)hi)[i] = h;
    ((uint2*)lo)[i] = l;
}

// ---------------------------------------------------------------------------
// Kernel: split-bf16 tensor-core GEMM.
// C[M,N] = Ah@Bh^T + Ah@Bl^T + Al@Bh^T + bias  (A,[M,K]; B,[N,K], bf16 planes)
// 128x128 CTA tile, BK=64, 2-stage cp.async pipeline, 8 warps of 64x32.
// ---------------------------------------------------------------------------
#define GSTAGE_BYTES 65536            // 4 planes x 16KB
#define GEMM_SMEM (2 * GSTAGE_BYTES)

__global__ __launch_bounds__(256, 1)
void gemm_bf16(const __nv_bfloat16* __restrict__ Ah,
               const __nv_bfloat16* __restrict__ Al,
               const __nv_bfloat16* __restrict__ Bh,
               const __nv_bfloat16* __restrict__ Bl,
               const float* __restrict__ bias, float* __restrict__ C,
               int M, int N, int K)
{
    extern __shared__ __align__(128) char smem[];
    const uint32_t sb = smem_u32(smem);
    const int tid = threadIdx.x, wid = tid >> 5, lane = tid & 31;
    const int brow = blockIdx.y * 128, bcol = blockIdx.x * 128;

    // loader: thread covers rows {j*32 + tid/8}, 16B segment (tid&7) per plane
    const int lrow = tid >> 3, lseg = tid & 7;
    uint32_t swoff[4], rowoffA[4], rowoffB[4];
#pragma unroll
    for (int j = 0; j < 4; j++) {
        int r = j * 32 + lrow;
        swoff[j]   = sw128((uint32_t)r * 128 + lseg * 16);
        rowoffA[j] = (uint32_t)min(brow + r, M - 1) * (uint32_t)K;
        rowoffB[j] = (uint32_t)(bcol + r) * (uint32_t)K;
    }
    const int esel = lseg * 8;   // element offset within k-chunk

    const __nv_bfloat16* pl[4] = {Ah, Al, Bh, Bl};

    auto issue = [&](int c) {
        const uint32_t sdst = sb + (c & 1) * GSTAGE_BYTES;
        const int ebase = c * 64 + esel;
#pragma unroll
        for (int i = 0; i < 16; i++) {
            const int plane = i >> 2, j = i & 3;
            const uint32_t roff = (plane < 2) ? rowoffA[j] : rowoffB[j];
            cp16(sdst + plane * 16384 + swoff[j], pl[plane] + (size_t)roff + ebase);
        }
        cp_commit();
    };

    issue(0);

    float acc[4][4][4];
#pragma unroll
    for (int a = 0; a < 4; a++)
#pragma unroll
        for (int b = 0; b < 4; b++)
#pragma unroll
            for (int cc = 0; cc < 4; cc++) acc[a][b][cc] = 0.f;

    const int wm = wid >> 2, wn = wid & 3;
    const int mb = wm * 64, nb = wn * 32;
    // ldmatrix lane partials
    const int laneA_row = mb + (lane & 15);
    const uint32_t laneA_k = (lane >> 4) * 16;
    const int laneB_row = nb + ((lane >> 4) << 3) + (lane & 7);
    const uint32_t laneB_k = ((lane >> 3) & 1) * 16;

    const int nCh = K >> 6;
    for (int c = 0; c < nCh; c++) {
        cp_wait0();
        __syncthreads();
        if (c + 1 < nCh) issue(c + 1);

        const uint32_t s = sb + (c & 1) * GSTAGE_BYTES;
#pragma unroll
        for (int ks = 0; ks < 4; ks++) {
            uint32_t bh[4][2], bl[4][2];
#pragma unroll
            for (int ntp = 0; ntp < 2; ntp++) {
                uint32_t byte = (uint32_t)(laneB_row + ntp * 16) * 128 + ks * 32 + laneB_k;
                uint32_t sw = sw128(byte);
                uint32_t r[4];
                ldm_x4(r, s + 32768 + sw);
                bh[2 * ntp][0] = r[0]; bh[2 * ntp][1] = r[1];
                bh[2 * ntp + 1][0] = r[2]; bh[2 * ntp + 1][1] = r[3];
                ldm_x4(r, s + 49152 + sw);
                bl[2 * ntp][0] = r[0]; bl[2 * ntp][1] = r[1];
                bl[2 * ntp + 1][0] = r[2]; bl[2 * ntp + 1][1] = r[3];
            }
#pragma unroll
            for (int mt = 0; mt < 4; mt++) {
                uint32_t byte = (uint32_t)(laneA_row + mt * 16) * 128 + ks * 32 + laneA_k;
                uint32_t sw = sw128(byte);
                uint32_t ah[4], al[4];
                ldm_x4(ah, s + sw);
                ldm_x4(al, s + 16384 + sw);
#pragma unroll
                for (int nt = 0; nt < 4; nt++) {
                    mma16816(acc[mt][nt], ah, bh[nt]);
                    mma16816(acc[mt][nt], ah, bl[nt]);
                    mma16816(acc[mt][nt], al, bh[nt]);
                }
            }
        }
    }

    // epilogue
#pragma unroll
    for (int mt = 0; mt < 4; mt++) {
        const int r0 = brow + mb + mt * 16 + (lane >> 2);
        const int r1 = r0 + 8;
#pragma unroll
        for (int nt = 0; nt < 4; nt++) {
            const int col = bcol + nb + nt * 8 + (lane & 3) * 2;
            float2 bv = *(const float2*)(bias + col);
            if (r0 < M) {
                float2 o = make_float2(acc[mt][nt][0] + bv.x, acc[mt][nt][1] + bv.y);
                *(float2*)(C + (size_t)r0 * N + col) = o;
            }
            if (r1 < M) {
                float2 o = make_float2(acc[mt][nt][2] + bv.x, acc[mt][nt][3] + bv.y);
                *(float2*)(C + (size_t)r1 * N + col) = o;
            }
        }
    }
}

// ---------------------------------------------------------------------------
// Kernel: flash-style sliding-window attention (fp32), writes hi/lo planes
// ---------------------------------------------------------------------------
__global__ __launch_bounds__(256)
void attn_kernel(const float* __restrict__ qkv,
                 __nv_bfloat16* __restrict__ oh,
                 __nv_bfloat16* __restrict__ ol)
{
    __shared__ float Qt[64][64];   // [d][q]
    __shared__ float KP[64][64];   // K^T then P
    __shared__ float Vs[64][64];   // [k][d]

    const int b  = blockIdx.z, h = blockIdx.y;
    const int qb = blockIdx.x * 64;
    const int tid = threadIdx.x;
    const int tx = tid & 15, ty = tid >> 4;
    const int q0 = ty * 4, k0 = tx * 4;

    const float* base = qkv + (size_t)b * T_ * QKVW_;

    for (int i = tid; i < 64 * 16; i += 256) {
        int q = i >> 4, seg = (i & 15) << 2;
        const float* qp = base + (size_t)(R_ + qb + q) * QKVW_ + h * HD_ + seg;
        float4 v = *(const float4*)qp;
        Qt[seg + 0][q] = v.x; Qt[seg + 1][q] = v.y;
        Qt[seg + 2][q] = v.z; Qt[seg + 3][q] = v.w;
    }

    float oacc[4][4];
    float m[4], l[4];
#pragma unroll
    for (int i = 0; i < 4; i++) {
        m[i] = -1e30f; l[i] = 0.f;
#pragma unroll
        for (int j = 0; j < 4; j++) oacc[i][j] = 0.f;
    }

    const int kstart = max(0, qb - HALF_);
    const int kend   = min(S_, qb + 64 + HALF_);
    const int nkeys  = R_ + (kend - kstart);
    const int nchunks = (nkeys + 63) >> 6;

    for (int c = 0; c < nchunks; c++) {
        __syncthreads();
        for (int i = tid; i < 64 * 16; i += 256) {
            int j = i >> 4, seg = (i & 15) << 2;
            int g = c * 64 + j;
            int row = (g < R_) ? g : (R_ + kstart + g - R_);
            if (g >= nkeys) row = 0;
            const float* kp = base + (size_t)row * QKVW_ + D_ + h * HD_ + seg;
            float4 kv = *(const float4*)kp;
            KP[seg + 0][j] = kv.x; KP[seg + 1][j] = kv.y;
            KP[seg + 2][j] = kv.z; KP[seg + 3][j] = kv.w;
            *(float4*)&Vs[j][seg] = *(const float4*)(kp + D_);
        }
        __syncthreads();

        float s[4][4];
#pragma unroll
        for (int i = 0; i < 4; i++)
#pragma unroll
            for (int j = 0; j < 4; j++) s[i][j] = 0.f;
#pragma unroll 8
        for (int kk = 0; kk < 64; kk++) {
            float4 qa = *(const float4*)&Qt[kk][q0];
            float4 kb = *(const float4*)&KP[kk][k0];
            float ra[4] = {qa.x, qa.y, qa.z, qa.w};
            float rb[4] = {kb.x, kb.y, kb.z, kb.w};
#pragma unroll
            for (int i = 0; i < 4; i++)
#pragma unroll
                for (int j = 0; j < 4; j++)
                    s[i][j] += ra[i] * rb[j];
        }

#pragma unroll
        for (int j = 0; j < 4; j++) {
            int g = c * 64 + k0 + j;
            int ktok = kstart + g - R_;
            bool isreg = g < R_;
            bool inb   = g < nkeys;
#pragma unroll
            for (int i = 0; i < 4; i++) {
                int qtok = qb + q0 + i;
                bool valid = inb && (isreg ||
                             (ktok >= qtok - HALF_ && ktok <= qtok + HALF_));
                s[i][j] = valid ? s[i][j] * 0.125f : -1e30f;
            }
        }

#pragma unroll
        for (int i = 0; i < 4; i++) {
            float cm = fmaxf(fmaxf(s[i][0], s[i][1]), fmaxf(s[i][2], s[i][3]));
            cm = fmaxf(cm, __shfl_xor_sync(0xffffffffu, cm, 1));
            cm = fmaxf(cm, __shfl_xor_sync(0xffffffffu, cm, 2));
            cm = fmaxf(cm, __shfl_xor_sync(0xffffffffu, cm, 4));
            cm = fmaxf(cm, __shfl_xor_sync(0xffffffffu, cm, 8));
            float mn = fmaxf(m[i], cm);
            float corr = __expf(m[i] - mn);
            float ps = 0.f;
#pragma unroll
            for (int j = 0; j < 4; j++) {
                s[i][j] = __expf(s[i][j] - mn);
                ps += s[i][j];
            }
            ps += __shfl_xor_sync(0xffffffffu, ps, 1);
            ps += __shfl_xor_sync(0xffffffffu, ps, 2);
            ps += __shfl_xor_sync(0xffffffffu, ps, 4);
            ps += __shfl_xor_sync(0xffffffffu, ps, 8);
            l[i] = l[i] * corr + ps;
#pragma unroll
            for (int j = 0; j < 4; j++) oacc[i][j] *= corr;
            m[i] = mn;
        }

        __syncthreads();
#pragma unroll
        for (int j = 0; j < 4; j++) {
            float4 pv = make_float4(s[0][j], s[1][j], s[2][j], s[3][j]);
            *(float4*)&KP[k0 + j][q0] = pv;
        }
        __syncthreads();

#pragma unroll 8
        for (int kk = 0; kk < 64; kk++) {
            float4 pa = *(const float4*)&KP[kk][q0];
            float4 vb = *(const float4*)&Vs[kk][k0];
            float ra[4] = {pa.x, pa.y, pa.z, pa.w};
            float rb[4] = {vb.x, vb.y, vb.z, vb.w};
#pragma unroll
            for (int i = 0; i < 4; i++)
#pragma unroll
                for (int j = 0; j < 4; j++)
                    oacc[i][j] += ra[i] * rb[j];
        }
    }

#pragma unroll
    for (int i = 0; i < 4; i++) {
        float inv = 1.0f / l[i];
        float4 o = make_float4(oacc[i][0] * inv, oacc[i][1] * inv,
                               oacc[i][2] * inv, oacc[i][3] * inv);
        uint2 hi, lo;
        split4(o, hi, lo);
        size_t idx = ((size_t)b * S_ + qb + q0 + i) * D_ + h * HD_ + k0;
        *(uint2*)(oh + idx) = hi;
        *(uint2*)(ol + idx) = lo;
    }
}

// ---------------------------------------------------------------------------
// Launch
// ---------------------------------------------------------------------------
extern "C" void kernel_launch(void* const* d_in, const int* in_sizes, int n_in,
                              void* d_out, int out_size)
{
    const float* x      = (const float*)d_in[0];
    const float* ada    = (const float*)d_in[1];
    const float* regs   = (const float*)d_in[2];
    const float* W_qkv  = (const float*)d_in[3];
    const float* b_qkv  = (const float*)d_in[4];
    const float* W_out  = (const float*)d_in[5];
    const float* b_out  = (const float*)d_in[6];
    float* out = (float*)d_out;

    __nv_bfloat16 *xrh, *xrl, *wqh, *wql, *woh, *wol, *ath, *atl;
    float* qkvbuf;
    cudaGetSymbolAddress((void**)&xrh, g_xr_hi);
    cudaGetSymbolAddress((void**)&xrl, g_xr_lo);
    cudaGetSymbolAddress((void**)&wqh, g_wq_hi);
    cudaGetSymbolAddress((void**)&wql, g_wq_lo);
    cudaGetSymbolAddress((void**)&woh, g_wo_hi);
    cudaGetSymbolAddress((void**)&wol, g_wo_lo);
    cudaGetSymbolAddress((void**)&ath, g_at_hi);
    cudaGetSymbolAddress((void**)&atl, g_at_lo);
    cudaGetSymbolAddress((void**)&qkvbuf, g_qkv);

    cudaFuncSetAttribute(gemm_bf16, cudaFuncAttributeMaxDynamicSharedMemorySize, GEMM_SMEM);

    // 1. splits
    const int n4 = B_ * T_ * (D_ / 4);
    build_xr_split<<<(n4 + 255) / 256, 256>>>(x, ada, regs, xrh, xrl);
    const int wq4 = QKVW_ * D_ / 4;
    split_planes<<<(wq4 + 255) / 256, 256>>>(W_qkv, wqh, wql, wq4);
    const int wo4 = D_ * D_ / 4;
    split_planes<<<(wo4 + 255) / 256, 256>>>(W_out, woh, wol, wo4);

    // 2. qkv = xr @ W_qkv^T + b_qkv : M=4112, N=3072, K=1024
    gemm_bf16<<<dim3(QKVW_ / 128, (B_ * T_ + 127) / 128), 256, GEMM_SMEM>>>(
        xrh, xrl, wqh, wql, b_qkv, qkvbuf, B_ * T_, QKVW_, D_);

    // 3. windowed attention -> hi/lo planes
    attn_kernel<<<dim3(S_ / 64, H_, B_), 256>>>(qkvbuf, ath, atl);

    // 4. out = attn @ W_out^T + b_out : M=4096, N=1024, K=1024
    gemm_bf16<<<dim3(D_ / 128, (B_ * S_) / 128), 256, GEMM_SMEM>>>(
        ath, atl, woh, wol, b_out, out, B_ * S_, D_, D_);
}

// round 6
// speedup vs baseline: 5.4426x; 1.5264x over previous
#include <cuda_runtime.h>
#include <cuda_bf16.h>
#include <math.h>
#include <stdint.h>

// Problem constants
#define B_   2
#define S_   2048
#define D_   1024
#define H_   16
#define HD_  64
#define R_   8
#define T_   2056      // S_ + R_
#define HALF_ 128
#define QKVW_ 3072     // 3*D_

// Scratch (device globals; no allocation allowed)
__device__ __align__(16) __nv_bfloat16 g_xr_hi[(size_t)B_ * T_ * D_];
__device__ __align__(16) __nv_bfloat16 g_xr_lo[(size_t)B_ * T_ * D_];
__device__ __align__(16) __nv_bfloat16 g_wq_hi[(size_t)QKVW_ * D_];
__device__ __align__(16) __nv_bfloat16 g_wq_lo[(size_t)QKVW_ * D_];
__device__ __align__(16) __nv_bfloat16 g_wo_hi[(size_t)D_ * D_];
__device__ __align__(16) __nv_bfloat16 g_wo_lo[(size_t)D_ * D_];
__device__ __align__(16) __nv_bfloat16 g_at_hi[(size_t)B_ * S_ * D_];
__device__ __align__(16) __nv_bfloat16 g_at_lo[(size_t)B_ * S_ * D_];
__device__ __align__(16) float g_qkv[(size_t)B_ * T_ * QKVW_];

// ---------------------------------------------------------------------------
// helpers
// ---------------------------------------------------------------------------
__device__ __forceinline__ uint32_t smem_u32(const void* p) {
    uint32_t a;
    asm("{ .reg .u64 t; cvta.to.shared.u64 t, %1; cvt.u32.u64 %0, t; }"
        : "=r"(a) : "l"(p));
    return a;
}
__device__ __forceinline__ uint32_t sw128(uint32_t off) {
    return off ^ ((off >> 3) & 0x70);
}
__device__ __forceinline__ void cp16(uint32_t dst, const void* src) {
    asm volatile("cp.async.cg.shared.global [%0], [%1], 16;"
                 :: "r"(dst), "l"(src) : "memory");
}
__device__ __forceinline__ void cp_commit() {
    asm volatile("cp.async.commit_group;" ::: "memory");
}
__device__ __forceinline__ void cp_wait0() {
    asm volatile("cp.async.wait_group 0;" ::: "memory");
}
__device__ __forceinline__ void ldm_x4(uint32_t* r, uint32_t addr) {
    asm volatile("ldmatrix.sync.aligned.m8n8.x4.shared.b16 {%0,%1,%2,%3}, [%4];"
                 : "=r"(r[0]), "=r"(r[1]), "=r"(r[2]), "=r"(r[3]) : "r"(addr));
}
__device__ __forceinline__ void ldm_x4_t(uint32_t* r, uint32_t addr) {
    asm volatile("ldmatrix.sync.aligned.m8n8.x4.trans.shared.b16 {%0,%1,%2,%3}, [%4];"
                 : "=r"(r[0]), "=r"(r[1]), "=r"(r[2]), "=r"(r[3]) : "r"(addr));
}
__device__ __forceinline__ void mma16816(float* c, const uint32_t* a, const uint32_t* b) {
    asm volatile(
        "mma.sync.aligned.m16n8k16.row.col.f32.bf16.bf16.f32 "
        "{%0,%1,%2,%3}, {%4,%5,%6,%7}, {%8,%9}, {%0,%1,%2,%3};"
        : "+f"(c[0]), "+f"(c[1]), "+f"(c[2]), "+f"(c[3])
        : "r"(a[0]), "r"(a[1]), "r"(a[2]), "r"(a[3]), "r"(b[0]), "r"(b[1]));
}

// pack 4 floats -> hi bf16x4 (uint2) and lo bf16x4 (uint2)
__device__ __forceinline__ void split4(float4 v, uint2& hi, uint2& lo) {
    __nv_bfloat16 h0 = __float2bfloat16_rn(v.x);
    __nv_bfloat16 h1 = __float2bfloat16_rn(v.y);
    __nv_bfloat16 h2 = __float2bfloat16_rn(v.z);
    __nv_bfloat16 h3 = __float2bfloat16_rn(v.w);
    hi.x = ((uint32_t)__bfloat16_as_ushort(h1) << 16) | __bfloat16_as_ushort(h0);
    hi.y = ((uint32_t)__bfloat16_as_ushort(h3) << 16) | __bfloat16_as_ushort(h2);
    __nv_bfloat162 l01 = __floats2bfloat162_rn(v.x - __bfloat162float(h0),
                                               v.y - __bfloat162float(h1));
    __nv_bfloat162 l23 = __floats2bfloat162_rn(v.z - __bfloat162float(h2),
                                               v.w - __bfloat162float(h3));
    lo.x = *(uint32_t*)&l01;
    lo.y = *(uint32_t*)&l23;
}
// pack 2 floats -> hi bf16x2 word and lo bf16x2 word
__device__ __forceinline__ void split2(float a, float b, uint32_t& hi, uint32_t& lo) {
    __nv_bfloat16 h0 = __float2bfloat16_rn(a);
    __nv_bfloat16 h1 = __float2bfloat16_rn(b);
    hi = ((uint32_t)__bfloat16_as_ushort(h1) << 16) | __bfloat16_as_ushort(h0);
    __nv_bfloat162 l = __floats2bfloat162_rn(a - __bfloat162float(h0),
                                             b - __bfloat162float(h1));
    lo = *(uint32_t*)&l;
}
__device__ __forceinline__ void sts8(uint32_t addr, uint2 v) {
    asm volatile("st.shared.v2.b32 [%0], {%1, %2};"
                 :: "r"(addr), "r"(v.x), "r"(v.y) : "memory");
}

// ---------------------------------------------------------------------------
// Kernel 1: build xr (hi/lo planes) = concat(registers*(1+ada), x)
// ---------------------------------------------------------------------------
__global__ void build_xr_split(const float* __restrict__ x,
                               const float* __restrict__ ada,
                               const float* __restrict__ regs,
                               __nv_bfloat16* __restrict__ xh,
                               __nv_bfloat16* __restrict__ xl)
{
    int i = blockIdx.x * blockDim.x + threadIdx.x;
    const int D4 = D_ / 4;
    if (i >= B_ * T_ * D4) return;
    int d4 = i % D4;
    int t  = (i / D4) % T_;
    int b  = i / (T_ * D4);
    float4 v;
    if (t < R_) {
        float4 rv = ((const float4*)regs)[t * D4 + d4];
        float4 av = ((const float4*)ada)[b * D4 + d4];
        v = make_float4(rv.x * (1.f + av.x), rv.y * (1.f + av.y),
                        rv.z * (1.f + av.z), rv.w * (1.f + av.w));
    } else {
        v = ((const float4*)x)[((size_t)b * S_ + (t - R_)) * D4 + d4];
    }
    uint2 hi, lo;
    split4(v, hi, lo);
    ((uint2*)xh)[i] = hi;
    ((uint2*)xl)[i] = lo;
}

// ---------------------------------------------------------------------------
// Kernel: generic fp32 -> (hi, lo) bf16 split
// ---------------------------------------------------------------------------
__global__ void split_planes(const float* __restrict__ src,
                             __nv_bfloat16* __restrict__ hi,
                             __nv_bfloat16* __restrict__ lo, int n4)
{
    int i = blockIdx.x * blockDim.x + threadIdx.x;
    if (i >= n4) return;
    float4 v = ((const float4*)src)[i];
    uint2 h, l;
    split4(v, h, l);
    ((uint2*)hi)[i] = h;
    ((uint2*)lo)[i] = l;
}

// ---------------------------------------------------------------------------
// Kernel: split-bf16 tensor-core GEMM (unchanged; known-good).
// ---------------------------------------------------------------------------
#define GSTAGE_BYTES 65536            // 4 planes x 16KB
#define GEMM_SMEM (2 * GSTAGE_BYTES)

__global__ __launch_bounds__(256, 1)
void gemm_bf16(const __nv_bfloat16* __restrict__ Ah,
               const __nv_bfloat16* __restrict__ Al,
               const __nv_bfloat16* __restrict__ Bh,
               const __nv_bfloat16* __restrict__ Bl,
               const float* __restrict__ bias, float* __restrict__ C,
               int M, int N, int K)
{
    extern __shared__ __align__(128) char smem[];
    const uint32_t sb = smem_u32(smem);
    const int tid = threadIdx.x, wid = tid >> 5, lane = tid & 31;
    const int brow = blockIdx.y * 128, bcol = blockIdx.x * 128;

    const int lrow = tid >> 3, lseg = tid & 7;
    uint32_t swoff[4], rowoffA[4], rowoffB[4];
#pragma unroll
    for (int j = 0; j < 4; j++) {
        int r = j * 32 + lrow;
        swoff[j]   = sw128((uint32_t)r * 128 + lseg * 16);
        rowoffA[j] = (uint32_t)min(brow + r, M - 1) * (uint32_t)K;
        rowoffB[j] = (uint32_t)(bcol + r) * (uint32_t)K;
    }
    const int esel = lseg * 8;

    const __nv_bfloat16* pl[4] = {Ah, Al, Bh, Bl};

    auto issue = [&](int c) {
        const uint32_t sdst = sb + (c & 1) * GSTAGE_BYTES;
        const int ebase = c * 64 + esel;
#pragma unroll
        for (int i = 0; i < 16; i++) {
            const int plane = i >> 2, j = i & 3;
            const uint32_t roff = (plane < 2) ? rowoffA[j] : rowoffB[j];
            cp16(sdst + plane * 16384 + swoff[j], pl[plane] + (size_t)roff + ebase);
        }
        cp_commit();
    };

    issue(0);

    float acc[4][4][4];
#pragma unroll
    for (int a = 0; a < 4; a++)
#pragma unroll
        for (int b = 0; b < 4; b++)
#pragma unroll
            for (int cc = 0; cc < 4; cc++) acc[a][b][cc] = 0.f;

    const int wm = wid >> 2, wn = wid & 3;
    const int mb = wm * 64, nb = wn * 32;
    const int laneA_row = mb + (lane & 15);
    const uint32_t laneA_k = (lane >> 4) * 16;
    const int laneB_row = nb + ((lane >> 4) << 3) + (lane & 7);
    const uint32_t laneB_k = ((lane >> 3) & 1) * 16;

    const int nCh = K >> 6;
    for (int c = 0; c < nCh; c++) {
        cp_wait0();
        __syncthreads();
        if (c + 1 < nCh) issue(c + 1);

        const uint32_t s = sb + (c & 1) * GSTAGE_BYTES;
#pragma unroll
        for (int ks = 0; ks < 4; ks++) {
            uint32_t bh[4][2], bl[4][2];
#pragma unroll
            for (int ntp = 0; ntp < 2; ntp++) {
                uint32_t byte = (uint32_t)(laneB_row + ntp * 16) * 128 + ks * 32 + laneB_k;
                uint32_t sw = sw128(byte);
                uint32_t r[4];
                ldm_x4(r, s + 32768 + sw);
                bh[2 * ntp][0] = r[0]; bh[2 * ntp][1] = r[1];
                bh[2 * ntp + 1][0] = r[2]; bh[2 * ntp + 1][1] = r[3];
                ldm_x4(r, s + 49152 + sw);
                bl[2 * ntp][0] = r[0]; bl[2 * ntp][1] = r[1];
                bl[2 * ntp + 1][0] = r[2]; bl[2 * ntp + 1][1] = r[3];
            }
#pragma unroll
            for (int mt = 0; mt < 4; mt++) {
                uint32_t byte = (uint32_t)(laneA_row + mt * 16) * 128 + ks * 32 + laneA_k;
                uint32_t sw = sw128(byte);
                uint32_t ah[4], al[4];
                ldm_x4(ah, s + sw);
                ldm_x4(al, s + 16384 + sw);
#pragma unroll
                for (int nt = 0; nt < 4; nt++) {
                    mma16816(acc[mt][nt], ah, bh[nt]);
                    mma16816(acc[mt][nt], ah, bl[nt]);
                    mma16816(acc[mt][nt], al, bh[nt]);
                }
            }
        }
    }

#pragma unroll
    for (int mt = 0; mt < 4; mt++) {
        const int r0 = brow + mb + mt * 16 + (lane >> 2);
        const int r1 = r0 + 8;
#pragma unroll
        for (int nt = 0; nt < 4; nt++) {
            const int col = bcol + nb + nt * 8 + (lane & 3) * 2;
            float2 bv = *(const float2*)(bias + col);
            if (r0 < M) {
                float2 o = make_float2(acc[mt][nt][0] + bv.x, acc[mt][nt][1] + bv.y);
                *(float2*)(C + (size_t)r0 * N + col) = o;
            }
            if (r1 < M) {
                float2 o = make_float2(acc[mt][nt][2] + bv.x, acc[mt][nt][3] + bv.y);
                *(float2*)(C + (size_t)r1 * N + col) = o;
            }
        }
    }
}

// ---------------------------------------------------------------------------
// Kernel: tensor-core sliding-window flash attention (split-bf16).
// Block = 64 queries x 1 head, 128 threads (4 warps; warp = 16q x 64keys).
// Chunk 0 = registers ONLY (rows 8-63 dummy, masked); chunk c>=1 row j =
// token kstart + (c-1)*64 + j  -- load mapping now matches mask mapping.
// ---------------------------------------------------------------------------
#define ATTN_SMEM 49152

__global__ __launch_bounds__(128)
void attn_tc(const float* __restrict__ qkv,
             __nv_bfloat16* __restrict__ oh,
             __nv_bfloat16* __restrict__ ol)
{
    extern __shared__ __align__(1024) char asmem[];
    const uint32_t sQh = smem_u32(asmem);
    const uint32_t sQl = sQh + 8192;
    const uint32_t sKh = sQh + 16384;
    const uint32_t sKl = sQh + 24576;
    const uint32_t sVh = sQh + 32768;
    const uint32_t sVl = sQh + 40960;

    const int b  = blockIdx.z, h = blockIdx.y;
    const int qb = blockIdx.x * 64;
    const int tid = threadIdx.x, warp = tid >> 5, lane = tid & 31;
    const float* base = qkv + (size_t)b * T_ * QKVW_ + h * HD_;

    // ---- load Q (64 rows x 64 dims fp32 -> split planes) ----
#pragma unroll
    for (int i = 0; i < 8; i++) {
        int slot = tid + i * 128;             // 0..1023
        int row = slot >> 4, seg = slot & 15; // seg: 4-float group
        float4 v = *(const float4*)(base + (size_t)(R_ + qb + row) * QKVW_ + seg * 4);
        uint2 hi, lo;
        split4(v, hi, lo);
        uint32_t off = sw128((uint32_t)row * 128 + seg * 8);
        sts8(sQh + off, hi);
        sts8(sQl + off, lo);
    }

    const int kstart = max(0, qb - HALF_);
    const int kend   = min(S_, qb + 64 + HALF_);
    const int nchunks = 1 + ((kend - kstart) >> 6);   // chunk 0 = regs only

    float oacc[8][4];
    float m[2] = {-1e30f, -1e30f}, lsum[2] = {0.f, 0.f};
#pragma unroll
    for (int nt = 0; nt < 8; nt++)
#pragma unroll
        for (int e = 0; e < 4; e++) oacc[nt][e] = 0.f;

    const int qtok0 = qb + warp * 16 + (lane >> 2);   // row 0 token
    const int laneA_row = warp * 16 + (lane & 15);
    const uint32_t laneA_k = (lane >> 4) * 16;

    for (int c = 0; c < nchunks; c++) {
        __syncthreads();
        // ---- load K,V chunk (64 rows each) ----
#pragma unroll
        for (int i = 0; i < 16; i++) {
            int slot = tid + i * 128;          // 0..2047
            int kv = slot >> 10;               // 0 = K, 1 = V
            int s2 = slot & 1023;
            int row = s2 >> 4, seg = s2 & 15;
            int grow;
            if (c == 0) grow = (row < R_) ? row : 0;                    // regs (+dummy)
            else        grow = R_ + kstart + (c - 1) * 64 + row;        // tokens
            const float* p = base + (size_t)grow * QKVW_ + (kv + 1) * D_ + seg * 4;
            float4 v = *(const float4*)p;
            uint2 hi, lo;
            split4(v, hi, lo);
            uint32_t off = sw128((uint32_t)row * 128 + seg * 8);
            sts8((kv ? sVh : sKh) + off, hi);
            sts8((kv ? sVl : sKl) + off, lo);
        }
        __syncthreads();

        // ---- S = Q K^T ----
        float sacc[8][4];
#pragma unroll
        for (int nt = 0; nt < 8; nt++)
#pragma unroll
            for (int e = 0; e < 4; e++) sacc[nt][e] = 0.f;

#pragma unroll
        for (int ks = 0; ks < 4; ks++) {
            uint32_t ah[4], al[4];
            uint32_t qoff = sw128((uint32_t)laneA_row * 128 + ks * 32 + laneA_k);
            ldm_x4(ah, sQh + qoff);
            ldm_x4(al, sQl + qoff);
            uint32_t bh[8][2], bl[8][2];
#pragma unroll
            for (int ntp = 0; ntp < 4; ntp++) {
                uint32_t row = ntp * 16 + ((lane >> 4) << 3) + (lane & 7);
                uint32_t off = sw128(row * 128 + ks * 32 + ((lane >> 3) & 1) * 16);
                uint32_t r[4];
                ldm_x4(r, sKh + off);
                bh[2 * ntp][0] = r[0]; bh[2 * ntp][1] = r[1];
                bh[2 * ntp + 1][0] = r[2]; bh[2 * ntp + 1][1] = r[3];
                ldm_x4(r, sKl + off);
                bl[2 * ntp][0] = r[0]; bl[2 * ntp][1] = r[1];
                bl[2 * ntp + 1][0] = r[2]; bl[2 * ntp + 1][1] = r[3];
            }
#pragma unroll
            for (int nt = 0; nt < 8; nt++) {
                mma16816(sacc[nt], ah, bh[nt]);
                mma16816(sacc[nt], ah, bl[nt]);
                mma16816(sacc[nt], al, bh[nt]);
            }
        }

        // ---- scale + mask (mapping matches loader) ----
        const int colbase = kstart + (c - 1) * 64;   // valid for c>0
        const int col2 = 2 * (lane & 3);
#pragma unroll
        for (int nt = 0; nt < 8; nt++) {
#pragma unroll
            for (int e = 0; e < 4; e++) {
                int klocal = nt * 8 + col2 + (e & 1);
                int qtok = qtok0 + (e >> 1) * 8;
                bool valid;
                if (c == 0) {
                    valid = klocal < R_;
                } else {
                    int ktok = colbase + klocal;
                    valid = (ktok >= qtok - HALF_) && (ktok <= qtok + HALF_);
                }
                sacc[nt][e] = valid ? sacc[nt][e] * 0.125f : -1e30f;
            }
        }

        // ---- online softmax (rows: lane/4 and lane/4+8) ----
        float mx[2] = {-1e30f, -1e30f};
#pragma unroll
        for (int nt = 0; nt < 8; nt++) {
            mx[0] = fmaxf(mx[0], fmaxf(sacc[nt][0], sacc[nt][1]));
            mx[1] = fmaxf(mx[1], fmaxf(sacc[nt][2], sacc[nt][3]));
        }
#pragma unroll
        for (int i = 0; i < 2; i++) {
            mx[i] = fmaxf(mx[i], __shfl_xor_sync(0xffffffffu, mx[i], 1));
            mx[i] = fmaxf(mx[i], __shfl_xor_sync(0xffffffffu, mx[i], 2));
        }
        float corr[2], ps[2] = {0.f, 0.f};
#pragma unroll
        for (int i = 0; i < 2; i++) {
            float mn = fmaxf(m[i], mx[i]);
            corr[i] = __expf(m[i] - mn);
            m[i] = mn;
        }
#pragma unroll
        for (int nt = 0; nt < 8; nt++) {
            sacc[nt][0] = __expf(sacc[nt][0] - m[0]);
            sacc[nt][1] = __expf(sacc[nt][1] - m[0]);
            sacc[nt][2] = __expf(sacc[nt][2] - m[1]);
            sacc[nt][3] = __expf(sacc[nt][3] - m[1]);
            ps[0] += sacc[nt][0] + sacc[nt][1];
            ps[1] += sacc[nt][2] + sacc[nt][3];
        }
#pragma unroll
        for (int i = 0; i < 2; i++) {
            ps[i] += __shfl_xor_sync(0xffffffffu, ps[i], 1);
            ps[i] += __shfl_xor_sync(0xffffffffu, ps[i], 2);
            lsum[i] = lsum[i] * corr[i] + ps[i];
        }
#pragma unroll
        for (int nt = 0; nt < 8; nt++) {
            oacc[nt][0] *= corr[0]; oacc[nt][1] *= corr[0];
            oacc[nt][2] *= corr[1]; oacc[nt][3] *= corr[1];
        }

        // ---- pack P into A fragments (hi/lo) ----
        uint32_t aph[4][4], apl[4][4];
#pragma unroll
        for (int ks = 0; ks < 4; ks++) {
            split2(sacc[2 * ks][0],     sacc[2 * ks][1],     aph[ks][0], apl[ks][0]);
            split2(sacc[2 * ks][2],     sacc[2 * ks][3],     aph[ks][1], apl[ks][1]);
            split2(sacc[2 * ks + 1][0], sacc[2 * ks + 1][1], aph[ks][2], apl[ks][2]);
            split2(sacc[2 * ks + 1][2], sacc[2 * ks + 1][3], aph[ks][3], apl[ks][3]);
        }

        // ---- O += P V ----
#pragma unroll
        for (int ks = 0; ks < 4; ks++) {
            uint32_t bvh[8][2], bvl[8][2];
#pragma unroll
            for (int ntp = 0; ntp < 4; ntp++) {
                uint32_t row = ks * 16 + ((lane >> 3) & 1) * 8 + (lane & 7);
                uint32_t off = sw128(row * 128 + ntp * 32 + (lane >> 4) * 16);
                uint32_t r[4];
                ldm_x4_t(r, sVh + off);
                bvh[2 * ntp][0] = r[0]; bvh[2 * ntp][1] = r[1];
                bvh[2 * ntp + 1][0] = r[2]; bvh[2 * ntp + 1][1] = r[3];
                ldm_x4_t(r, sVl + off);
                bvl[2 * ntp][0] = r[0]; bvl[2 * ntp][1] = r[1];
                bvl[2 * ntp + 1][0] = r[2]; bvl[2 * ntp + 1][1] = r[3];
            }
#pragma unroll
            for (int nt = 0; nt < 8; nt++) {
                mma16816(oacc[nt], aph[ks], bvh[nt]);
                mma16816(oacc[nt], aph[ks], bvl[nt]);
                mma16816(oacc[nt], apl[ks], bvh[nt]);
            }
        }
    }

    // ---- normalize + write hi/lo planes ----
    const float inv0 = 1.0f / lsum[0];
    const float inv1 = 1.0f / lsum[1];
    const int tok0 = qb + warp * 16 + (lane >> 2);
#pragma unroll
    for (int nt = 0; nt < 8; nt++) {
        const int d0 = nt * 8 + 2 * (lane & 3);
        size_t i0 = ((size_t)b * S_ + tok0) * D_ + h * HD_ + d0;
        size_t i1 = ((size_t)b * S_ + tok0 + 8) * D_ + h * HD_ + d0;
        uint32_t hi, lo;
        split2(oacc[nt][0] * inv0, oacc[nt][1] * inv0, hi, lo);
        *(uint32_t*)(oh + i0) = hi;
        *(uint32_t*)(ol + i0) = lo;
        split2(oacc[nt][2] * inv1, oacc[nt][3] * inv1, hi, lo);
        *(uint32_t*)(oh + i1) = hi;
        *(uint32_t*)(ol + i1) = lo;
    }
}

// ---------------------------------------------------------------------------
// Launch
// ---------------------------------------------------------------------------
extern "C" void kernel_launch(void* const* d_in, const int* in_sizes, int n_in,
                              void* d_out, int out_size)
{
    const float* x      = (const float*)d_in[0];
    const float* ada    = (const float*)d_in[1];
    const float* regs   = (const float*)d_in[2];
    const float* W_qkv  = (const float*)d_in[3];
    const float* b_qkv  = (const float*)d_in[4];
    const float* W_out  = (const float*)d_in[5];
    const float* b_out  = (const float*)d_in[6];
    float* out = (float*)d_out;

    __nv_bfloat16 *xrh, *xrl, *wqh, *wql, *woh, *wol, *ath, *atl;
    float* qkvbuf;
    cudaGetSymbolAddress((void**)&xrh, g_xr_hi);
    cudaGetSymbolAddress((void**)&xrl, g_xr_lo);
    cudaGetSymbolAddress((void**)&wqh, g_wq_hi);
    cudaGetSymbolAddress((void**)&wql, g_wq_lo);
    cudaGetSymbolAddress((void**)&woh, g_wo_hi);
    cudaGetSymbolAddress((void**)&wol, g_wo_lo);
    cudaGetSymbolAddress((void**)&ath, g_at_hi);
    cudaGetSymbolAddress((void**)&atl, g_at_lo);
    cudaGetSymbolAddress((void**)&qkvbuf, g_qkv);

    cudaFuncSetAttribute(gemm_bf16, cudaFuncAttributeMaxDynamicSharedMemorySize, GEMM_SMEM);
    cudaFuncSetAttribute(attn_tc, cudaFuncAttributeMaxDynamicSharedMemorySize, ATTN_SMEM);

    // 1. splits
    const int n4 = B_ * T_ * (D_ / 4);
    build_xr_split<<<(n4 + 255) / 256, 256>>>(x, ada, regs, xrh, xrl);
    const int wq4 = QKVW_ * D_ / 4;
    split_planes<<<(wq4 + 255) / 256, 256>>>(W_qkv, wqh, wql, wq4);
    const int wo4 = D_ * D_ / 4;
    split_planes<<<(wo4 + 255) / 256, 256>>>(W_out, woh, wol, wo4);

    // 2. qkv = xr @ W_qkv^T + b_qkv : M=4112, N=3072, K=1024
    gemm_bf16<<<dim3(QKVW_ / 128, (B_ * T_ + 127) / 128), 256, GEMM_SMEM>>>(
        xrh, xrl, wqh, wql, b_qkv, qkvbuf, B_ * T_, QKVW_, D_);

    // 3. windowed attention (tensor cores) -> hi/lo planes
    attn_tc<<<dim3(S_ / 64, H_, B_), 128, ATTN_SMEM>>>(qkvbuf, ath, atl);

    // 4. out = attn @ W_out^T + b_out : M=4096, N=1024, K=1024
    gemm_bf16<<<dim3(D_ / 128, (B_ * S_) / 128), 256, GEMM_SMEM>>>(
        ath, atl, woh, wol, b_out, out, B_ * S_, D_, D_);
}

// round 7
// speedup vs baseline: 5.6186x; 1.0323x over previous
#include <cuda_runtime.h>
#include <cuda_bf16.h>
#include <math.h>
#include <stdint.h>

// Problem constants
#define B_   2
#define S_   2048
#define D_   1024
#define H_   16
#define HD_  64
#define R_   8
#define T_   2056      // S_ + R_
#define HALF_ 128
#define QKVW_ 3072     // 3*D_

// Scratch (device globals; no allocation allowed)
__device__ __align__(16) __nv_bfloat16 g_xr_hi[(size_t)B_ * T_ * D_];
__device__ __align__(16) __nv_bfloat16 g_xr_lo[(size_t)B_ * T_ * D_];
__device__ __align__(16) __nv_bfloat16 g_wq_hi[(size_t)QKVW_ * D_];
__device__ __align__(16) __nv_bfloat16 g_wq_lo[(size_t)QKVW_ * D_];
__device__ __align__(16) __nv_bfloat16 g_wo_hi[(size_t)D_ * D_];
__device__ __align__(16) __nv_bfloat16 g_wo_lo[(size_t)D_ * D_];
__device__ __align__(16) __nv_bfloat16 g_at_hi[(size_t)B_ * S_ * D_];
__device__ __align__(16) __nv_bfloat16 g_at_lo[(size_t)B_ * S_ * D_];
__device__ __align__(16) float g_qkv[(size_t)B_ * T_ * QKVW_];

// ---------------------------------------------------------------------------
// helpers
// ---------------------------------------------------------------------------
__device__ __forceinline__ uint32_t smem_u32(const void* p) {
    uint32_t a;
    asm("{ .reg .u64 t; cvta.to.shared.u64 t, %1; cvt.u32.u64 %0, t; }"
        : "=r"(a) : "l"(p));
    return a;
}
__device__ __forceinline__ uint32_t sw128(uint32_t off) {
    return off ^ ((off >> 3) & 0x70);
}
__device__ __forceinline__ void cp16(uint32_t dst, const void* src) {
    asm volatile("cp.async.cg.shared.global [%0], [%1], 16;"
                 :: "r"(dst), "l"(src) : "memory");
}
__device__ __forceinline__ void cp_commit() {
    asm volatile("cp.async.commit_group;" ::: "memory");
}
__device__ __forceinline__ void cp_wait0() {
    asm volatile("cp.async.wait_group 0;" ::: "memory");
}
__device__ __forceinline__ void ldm_x4(uint32_t* r, uint32_t addr) {
    asm volatile("ldmatrix.sync.aligned.m8n8.x4.shared.b16 {%0,%1,%2,%3}, [%4];"
                 : "=r"(r[0]), "=r"(r[1]), "=r"(r[2]), "=r"(r[3]) : "r"(addr));
}
__device__ __forceinline__ void ldm_x4_t(uint32_t* r, uint32_t addr) {
    asm volatile("ldmatrix.sync.aligned.m8n8.x4.trans.shared.b16 {%0,%1,%2,%3}, [%4];"
                 : "=r"(r[0]), "=r"(r[1]), "=r"(r[2]), "=r"(r[3]) : "r"(addr));
}
__device__ __forceinline__ void mma16816(float* c, const uint32_t* a, const uint32_t* b) {
    asm volatile(
        "mma.sync.aligned.m16n8k16.row.col.f32.bf16.bf16.f32 "
        "{%0,%1,%2,%3}, {%4,%5,%6,%7}, {%8,%9}, {%0,%1,%2,%3};"
        : "+f"(c[0]), "+f"(c[1]), "+f"(c[2]), "+f"(c[3])
        : "r"(a[0]), "r"(a[1]), "r"(a[2]), "r"(a[3]), "r"(b[0]), "r"(b[1]));
}

// pack 4 floats -> hi bf16x4 (uint2) and lo bf16x4 (uint2)
__device__ __forceinline__ void split4(float4 v, uint2& hi, uint2& lo) {
    __nv_bfloat16 h0 = __float2bfloat16_rn(v.x);
    __nv_bfloat16 h1 = __float2bfloat16_rn(v.y);
    __nv_bfloat16 h2 = __float2bfloat16_rn(v.z);
    __nv_bfloat16 h3 = __float2bfloat16_rn(v.w);
    hi.x = ((uint32_t)__bfloat16_as_ushort(h1) << 16) | __bfloat16_as_ushort(h0);
    hi.y = ((uint32_t)__bfloat16_as_ushort(h3) << 16) | __bfloat16_as_ushort(h2);
    __nv_bfloat162 l01 = __floats2bfloat162_rn(v.x - __bfloat162float(h0),
                                               v.y - __bfloat162float(h1));
    __nv_bfloat162 l23 = __floats2bfloat162_rn(v.z - __bfloat162float(h2),
                                               v.w - __bfloat162float(h3));
    lo.x = *(uint32_t*)&l01;
    lo.y = *(uint32_t*)&l23;
}
// pack 2 floats -> hi bf16x2 word and lo bf16x2 word
__device__ __forceinline__ void split2(float a, float b, uint32_t& hi, uint32_t& lo) {
    __nv_bfloat16 h0 = __float2bfloat16_rn(a);
    __nv_bfloat16 h1 = __float2bfloat16_rn(b);
    hi = ((uint32_t)__bfloat16_as_ushort(h1) << 16) | __bfloat16_as_ushort(h0);
    __nv_bfloat162 l = __floats2bfloat162_rn(a - __bfloat162float(h0),
                                             b - __bfloat162float(h1));
    lo = *(uint32_t*)&l;
}
__device__ __forceinline__ void sts8(uint32_t addr, uint2 v) {
    asm volatile("st.shared.v2.b32 [%0], {%1, %2};"
                 :: "r"(addr), "r"(v.x), "r"(v.y) : "memory");
}

// ---------------------------------------------------------------------------
// Kernel 1: build xr (hi/lo planes) = concat(registers*(1+ada), x)
// ---------------------------------------------------------------------------
__global__ void build_xr_split(const float* __restrict__ x,
                               const float* __restrict__ ada,
                               const float* __restrict__ regs,
                               __nv_bfloat16* __restrict__ xh,
                               __nv_bfloat16* __restrict__ xl)
{
    int i = blockIdx.x * blockDim.x + threadIdx.x;
    const int D4 = D_ / 4;
    if (i >= B_ * T_ * D4) return;
    int d4 = i % D4;
    int t  = (i / D4) % T_;
    int b  = i / (T_ * D4);
    float4 v;
    if (t < R_) {
        float4 rv = ((const float4*)regs)[t * D4 + d4];
        float4 av = ((const float4*)ada)[b * D4 + d4];
        v = make_float4(rv.x * (1.f + av.x), rv.y * (1.f + av.y),
                        rv.z * (1.f + av.z), rv.w * (1.f + av.w));
    } else {
        v = ((const float4*)x)[((size_t)b * S_ + (t - R_)) * D4 + d4];
    }
    uint2 hi, lo;
    split4(v, hi, lo);
    ((uint2*)xh)[i] = hi;
    ((uint2*)xl)[i] = lo;
}

// ---------------------------------------------------------------------------
// Kernel: generic fp32 -> (hi, lo) bf16 split
// ---------------------------------------------------------------------------
__global__ void split_planes(const float* __restrict__ src,
                             __nv_bfloat16* __restrict__ hi,
                             __nv_bfloat16* __restrict__ lo, int n4)
{
    int i = blockIdx.x * blockDim.x + threadIdx.x;
    if (i >= n4) return;
    float4 v = ((const float4*)src)[i];
    uint2 h, l;
    split4(v, h, l);
    ((uint2*)hi)[i] = h;
    ((uint2*)lo)[i] = l;
}

// ---------------------------------------------------------------------------
// Kernel: split-bf16 tensor-core GEMM, 256x128 CTA tile.
// C[M,N] = Ah@Bh^T + Ah@Bl^T + Al@Bh^T + bias.
// 8 warps as 4(M) x 2(N); warp tile 64x64. BK=64, 2-stage cp.async pipeline.
// Stage layout: [Ah 32K][Al 32K][Bh 16K][Bl 16K] = 96KB; 2 stages = 192KB.
// ---------------------------------------------------------------------------
#define GSTAGE_BYTES 98304
#define GEMM_SMEM (2 * GSTAGE_BYTES)

__global__ __launch_bounds__(256, 1)
void gemm_bf16(const __nv_bfloat16* __restrict__ Ah,
               const __nv_bfloat16* __restrict__ Al,
               const __nv_bfloat16* __restrict__ Bh,
               const __nv_bfloat16* __restrict__ Bl,
               const float* __restrict__ bias, float* __restrict__ C,
               int M, int N, int K)
{
    extern __shared__ __align__(128) char smem[];
    const uint32_t sb = smem_u32(smem);
    const int tid = threadIdx.x, wid = tid >> 5, lane = tid & 31;
    const int brow = blockIdx.y * 256, bcol = blockIdx.x * 128;

    // loader: thread handles seg (tid&7), rows r0 + j*32
    const int r0 = tid >> 3, lseg = tid & 7;
    uint32_t aOff[8], bOff[4], swO[8];
#pragma unroll
    for (int j = 0; j < 8; j++) {
        int r = r0 + j * 32;
        swO[j]  = sw128((uint32_t)r * 128 + lseg * 16);
        aOff[j] = (uint32_t)min(brow + r, M - 1) * (uint32_t)K;
        if (j < 4) bOff[j] = (uint32_t)(bcol + r) * (uint32_t)K;
    }
    const int esel = lseg * 8;

    auto issue = [&](int c) {
        const uint32_t sdst = sb + (c & 1) * GSTAGE_BYTES;
        const int ebase = c * 64 + esel;
#pragma unroll
        for (int j = 0; j < 8; j++) {
            cp16(sdst +         swO[j], Ah + (size_t)aOff[j] + ebase);
            cp16(sdst + 32768 + swO[j], Al + (size_t)aOff[j] + ebase);
        }
#pragma unroll
        for (int j = 0; j < 4; j++) {
            cp16(sdst + 65536 + swO[j], Bh + (size_t)bOff[j] + ebase);
            cp16(sdst + 81920 + swO[j], Bl + (size_t)bOff[j] + ebase);
        }
        cp_commit();
    };

    issue(0);

    float acc[4][8][4];
#pragma unroll
    for (int a = 0; a < 4; a++)
#pragma unroll
        for (int b = 0; b < 8; b++)
#pragma unroll
            for (int cc = 0; cc < 4; cc++) acc[a][b][cc] = 0.f;

    const int mb = (wid >> 1) * 64, nb = (wid & 1) * 64;
    const int laneA_row = mb + (lane & 15);
    const uint32_t laneA_k = (lane >> 4) * 16;
    const int laneB_row = nb + ((lane >> 4) << 3) + (lane & 7);
    const uint32_t laneB_k = ((lane >> 3) & 1) * 16;

    const int nCh = K >> 6;
    for (int c = 0; c < nCh; c++) {
        cp_wait0();
        __syncthreads();
        if (c + 1 < nCh) issue(c + 1);

        const uint32_t s = sb + (c & 1) * GSTAGE_BYTES;
#pragma unroll
        for (int ks = 0; ks < 4; ks++) {
            uint32_t bh[8][2], bl[8][2];
#pragma unroll
            for (int ntp = 0; ntp < 4; ntp++) {
                uint32_t byte = (uint32_t)(laneB_row + ntp * 16) * 128 + ks * 32 + laneB_k;
                uint32_t sw = sw128(byte);
                uint32_t r[4];
                ldm_x4(r, s + 65536 + sw);
                bh[2 * ntp][0] = r[0]; bh[2 * ntp][1] = r[1];
                bh[2 * ntp + 1][0] = r[2]; bh[2 * ntp + 1][1] = r[3];
                ldm_x4(r, s + 81920 + sw);
                bl[2 * ntp][0] = r[0]; bl[2 * ntp][1] = r[1];
                bl[2 * ntp + 1][0] = r[2]; bl[2 * ntp + 1][1] = r[3];
            }
#pragma unroll
            for (int mt = 0; mt < 4; mt++) {
                uint32_t byte = (uint32_t)(laneA_row + mt * 16) * 128 + ks * 32 + laneA_k;
                uint32_t sw = sw128(byte);
                uint32_t ah[4], al[4];
                ldm_x4(ah, s + sw);
                ldm_x4(al, s + 32768 + sw);
#pragma unroll
                for (int nt = 0; nt < 8; nt++) {
                    mma16816(acc[mt][nt], ah, bh[nt]);
                    mma16816(acc[mt][nt], ah, bl[nt]);
                    mma16816(acc[mt][nt], al, bh[nt]);
                }
            }
        }
    }

#pragma unroll
    for (int mt = 0; mt < 4; mt++) {
        const int rr0 = brow + mb + mt * 16 + (lane >> 2);
        const int rr1 = rr0 + 8;
#pragma unroll
        for (int nt = 0; nt < 8; nt++) {
            const int col = bcol + nb + nt * 8 + (lane & 3) * 2;
            float2 bv = *(const float2*)(bias + col);
            if (rr0 < M) {
                float2 o = make_float2(acc[mt][nt][0] + bv.x, acc[mt][nt][1] + bv.y);
                *(float2*)(C + (size_t)rr0 * N + col) = o;
            }
            if (rr1 < M) {
                float2 o = make_float2(acc[mt][nt][2] + bv.x, acc[mt][nt][3] + bv.y);
                *(float2*)(C + (size_t)rr1 * N + col) = o;
            }
        }
    }
}

// ---------------------------------------------------------------------------
// Kernel: tensor-core sliding-window flash attention (split-bf16).
// (unchanged from R6 -- known good)
// ---------------------------------------------------------------------------
#define ATTN_SMEM 49152

__global__ __launch_bounds__(128)
void attn_tc(const float* __restrict__ qkv,
             __nv_bfloat16* __restrict__ oh,
             __nv_bfloat16* __restrict__ ol)
{
    extern __shared__ __align__(1024) char asmem[];
    const uint32_t sQh = smem_u32(asmem);
    const uint32_t sQl = sQh + 8192;
    const uint32_t sKh = sQh + 16384;
    const uint32_t sKl = sQh + 24576;
    const uint32_t sVh = sQh + 32768;
    const uint32_t sVl = sQh + 40960;

    const int b  = blockIdx.z, h = blockIdx.y;
    const int qb = blockIdx.x * 64;
    const int tid = threadIdx.x, warp = tid >> 5, lane = tid & 31;
    const float* base = qkv + (size_t)b * T_ * QKVW_ + h * HD_;

#pragma unroll
    for (int i = 0; i < 8; i++) {
        int slot = tid + i * 128;
        int row = slot >> 4, seg = slot & 15;
        float4 v = *(const float4*)(base + (size_t)(R_ + qb + row) * QKVW_ + seg * 4);
        uint2 hi, lo;
        split4(v, hi, lo);
        uint32_t off = sw128((uint32_t)row * 128 + seg * 8);
        sts8(sQh + off, hi);
        sts8(sQl + off, lo);
    }

    const int kstart = max(0, qb - HALF_);
    const int kend   = min(S_, qb + 64 + HALF_);
    const int nchunks = 1 + ((kend - kstart) >> 6);   // chunk 0 = regs only

    float oacc[8][4];
    float m[2] = {-1e30f, -1e30f}, lsum[2] = {0.f, 0.f};
#pragma unroll
    for (int nt = 0; nt < 8; nt++)
#pragma unroll
        for (int e = 0; e < 4; e++) oacc[nt][e] = 0.f;

    const int qtok0 = qb + warp * 16 + (lane >> 2);
    const int laneA_row = warp * 16 + (lane & 15);
    const uint32_t laneA_k = (lane >> 4) * 16;

    for (int c = 0; c < nchunks; c++) {
        __syncthreads();
#pragma unroll
        for (int i = 0; i < 16; i++) {
            int slot = tid + i * 128;
            int kv = slot >> 10;
            int s2 = slot & 1023;
            int row = s2 >> 4, seg = s2 & 15;
            int grow;
            if (c == 0) grow = (row < R_) ? row : 0;
            else        grow = R_ + kstart + (c - 1) * 64 + row;
            const float* p = base + (size_t)grow * QKVW_ + (kv + 1) * D_ + seg * 4;
            float4 v = *(const float4*)p;
            uint2 hi, lo;
            split4(v, hi, lo);
            uint32_t off = sw128((uint32_t)row * 128 + seg * 8);
            sts8((kv ? sVh : sKh) + off, hi);
            sts8((kv ? sVl : sKl) + off, lo);
        }
        __syncthreads();

        float sacc[8][4];
#pragma unroll
        for (int nt = 0; nt < 8; nt++)
#pragma unroll
            for (int e = 0; e < 4; e++) sacc[nt][e] = 0.f;

#pragma unroll
        for (int ks = 0; ks < 4; ks++) {
            uint32_t ah[4], al[4];
            uint32_t qoff = sw128((uint32_t)laneA_row * 128 + ks * 32 + laneA_k);
            ldm_x4(ah, sQh + qoff);
            ldm_x4(al, sQl + qoff);
            uint32_t bh[8][2], bl[8][2];
#pragma unroll
            for (int ntp = 0; ntp < 4; ntp++) {
                uint32_t row = ntp * 16 + ((lane >> 4) << 3) + (lane & 7);
                uint32_t off = sw128(row * 128 + ks * 32 + ((lane >> 3) & 1) * 16);
                uint32_t r[4];
                ldm_x4(r, sKh + off);
                bh[2 * ntp][0] = r[0]; bh[2 * ntp][1] = r[1];
                bh[2 * ntp + 1][0] = r[2]; bh[2 * ntp + 1][1] = r[3];
                ldm_x4(r, sKl + off);
                bl[2 * ntp][0] = r[0]; bl[2 * ntp][1] = r[1];
                bl[2 * ntp + 1][0] = r[2]; bl[2 * ntp + 1][1] = r[3];
            }
#pragma unroll
            for (int nt = 0; nt < 8; nt++) {
                mma16816(sacc[nt], ah, bh[nt]);
                mma16816(sacc[nt], ah, bl[nt]);
                mma16816(sacc[nt], al, bh[nt]);
            }
        }

        const int colbase = kstart + (c - 1) * 64;
        const int col2 = 2 * (lane & 3);
#pragma unroll
        for (int nt = 0; nt < 8; nt++) {
#pragma unroll
            for (int e = 0; e < 4; e++) {
                int klocal = nt * 8 + col2 + (e & 1);
                int qtok = qtok0 + (e >> 1) * 8;
                bool valid;
                if (c == 0) {
                    valid = klocal < R_;
                } else {
                    int ktok = colbase + klocal;
                    valid = (ktok >= qtok - HALF_) && (ktok <= qtok + HALF_);
                }
                sacc[nt][e] = valid ? sacc[nt][e] * 0.125f : -1e30f;
            }
        }

        float mx[2] = {-1e30f, -1e30f};
#pragma unroll
        for (int nt = 0; nt < 8; nt++) {
            mx[0] = fmaxf(mx[0], fmaxf(sacc[nt][0], sacc[nt][1]));
            mx[1] = fmaxf(mx[1], fmaxf(sacc[nt][2], sacc[nt][3]));
        }
#pragma unroll
        for (int i = 0; i < 2; i++) {
            mx[i] = fmaxf(mx[i], __shfl_xor_sync(0xffffffffu, mx[i], 1));
            mx[i] = fmaxf(mx[i], __shfl_xor_sync(0xffffffffu, mx[i], 2));
        }
        float corr[2], ps[2] = {0.f, 0.f};
#pragma unroll
        for (int i = 0; i < 2; i++) {
            float mn = fmaxf(m[i], mx[i]);
            corr[i] = __expf(m[i] - mn);
            m[i] = mn;
        }
#pragma unroll
        for (int nt = 0; nt < 8; nt++) {
            sacc[nt][0] = __expf(sacc[nt][0] - m[0]);
            sacc[nt][1] = __expf(sacc[nt][1] - m[0]);
            sacc[nt][2] = __expf(sacc[nt][2] - m[1]);
            sacc[nt][3] = __expf(sacc[nt][3] - m[1]);
            ps[0] += sacc[nt][0] + sacc[nt][1];
            ps[1] += sacc[nt][2] + sacc[nt][3];
        }
#pragma unroll
        for (int i = 0; i < 2; i++) {
            ps[i] += __shfl_xor_sync(0xffffffffu, ps[i], 1);
            ps[i] += __shfl_xor_sync(0xffffffffu, ps[i], 2);
            lsum[i] = lsum[i] * corr[i] + ps[i];
        }
#pragma unroll
        for (int nt = 0; nt < 8; nt++) {
            oacc[nt][0] *= corr[0]; oacc[nt][1] *= corr[0];
            oacc[nt][2] *= corr[1]; oacc[nt][3] *= corr[1];
        }

        uint32_t aph[4][4], apl[4][4];
#pragma unroll
        for (int ks = 0; ks < 4; ks++) {
            split2(sacc[2 * ks][0],     sacc[2 * ks][1],     aph[ks][0], apl[ks][0]);
            split2(sacc[2 * ks][2],     sacc[2 * ks][3],     aph[ks][1], apl[ks][1]);
            split2(sacc[2 * ks + 1][0], sacc[2 * ks + 1][1], aph[ks][2], apl[ks][2]);
            split2(sacc[2 * ks + 1][2], sacc[2 * ks + 1][3], aph[ks][3], apl[ks][3]);
        }

#pragma unroll
        for (int ks = 0; ks < 4; ks++) {
            uint32_t bvh[8][2], bvl[8][2];
#pragma unroll
            for (int ntp = 0; ntp < 4; ntp++) {
                uint32_t row = ks * 16 + ((lane >> 3) & 1) * 8 + (lane & 7);
                uint32_t off = sw128(row * 128 + ntp * 32 + (lane >> 4) * 16);
                uint32_t r[4];
                ldm_x4_t(r, sVh + off);
                bvh[2 * ntp][0] = r[0]; bvh[2 * ntp][1] = r[1];
                bvh[2 * ntp + 1][0] = r[2]; bvh[2 * ntp + 1][1] = r[3];
                ldm_x4_t(r, sVl + off);
                bvl[2 * ntp][0] = r[0]; bvl[2 * ntp][1] = r[1];
                bvl[2 * ntp + 1][0] = r[2]; bvl[2 * ntp + 1][1] = r[3];
            }
#pragma unroll
            for (int nt = 0; nt < 8; nt++) {
                mma16816(oacc[nt], aph[ks], bvh[nt]);
                mma16816(oacc[nt], aph[ks], bvl[nt]);
                mma16816(oacc[nt], apl[ks], bvh[nt]);
            }
        }
    }

    const float inv0 = 1.0f / lsum[0];
    const float inv1 = 1.0f / lsum[1];
    const int tok0 = qb + warp * 16 + (lane >> 2);
#pragma unroll
    for (int nt = 0; nt < 8; nt++) {
        const int d0 = nt * 8 + 2 * (lane & 3);
        size_t i0 = ((size_t)b * S_ + tok0) * D_ + h * HD_ + d0;
        size_t i1 = ((size_t)b * S_ + tok0 + 8) * D_ + h * HD_ + d0;
        uint32_t hi, lo;
        split2(oacc[nt][0] * inv0, oacc[nt][1] * inv0, hi, lo);
        *(uint32_t*)(oh + i0) = hi;
        *(uint32_t*)(ol + i0) = lo;
        split2(oacc[nt][2] * inv1, oacc[nt][3] * inv1, hi, lo);
        *(uint32_t*)(oh + i1) = hi;
        *(uint32_t*)(ol + i1) = lo;
    }
}

// ---------------------------------------------------------------------------
// Launch
// ---------------------------------------------------------------------------
extern "C" void kernel_launch(void* const* d_in, const int* in_sizes, int n_in,
                              void* d_out, int out_size)
{
    const float* x      = (const float*)d_in[0];
    const float* ada    = (const float*)d_in[1];
    const float* regs   = (const float*)d_in[2];
    const float* W_qkv  = (const float*)d_in[3];
    const float* b_qkv  = (const float*)d_in[4];
    const float* W_out  = (const float*)d_in[5];
    const float* b_out  = (const float*)d_in[6];
    float* out = (float*)d_out;

    __nv_bfloat16 *xrh, *xrl, *wqh, *wql, *woh, *wol, *ath, *atl;
    float* qkvbuf;
    cudaGetSymbolAddress((void**)&xrh, g_xr_hi);
    cudaGetSymbolAddress((void**)&xrl, g_xr_lo);
    cudaGetSymbolAddress((void**)&wqh, g_wq_hi);
    cudaGetSymbolAddress((void**)&wql, g_wq_lo);
    cudaGetSymbolAddress((void**)&woh, g_wo_hi);
    cudaGetSymbolAddress((void**)&wol, g_wo_lo);
    cudaGetSymbolAddress((void**)&ath, g_at_hi);
    cudaGetSymbolAddress((void**)&atl, g_at_lo);
    cudaGetSymbolAddress((void**)&qkvbuf, g_qkv);

    cudaFuncSetAttribute(gemm_bf16, cudaFuncAttributeMaxDynamicSharedMemorySize, GEMM_SMEM);
    cudaFuncSetAttribute(attn_tc, cudaFuncAttributeMaxDynamicSharedMemorySize, ATTN_SMEM);

    // 1. splits
    const int n4 = B_ * T_ * (D_ / 4);
    build_xr_split<<<(n4 + 255) / 256, 256>>>(x, ada, regs, xrh, xrl);
    const int wq4 = QKVW_ * D_ / 4;
    split_planes<<<(wq4 + 255) / 256, 256>>>(W_qkv, wqh, wql, wq4);
    const int wo4 = D_ * D_ / 4;
    split_planes<<<(wo4 + 255) / 256, 256>>>(W_out, woh, wol, wo4);

    // 2. qkv = xr @ W_qkv^T + b_qkv : M=4112, N=3072, K=1024
    gemm_bf16<<<dim3(QKVW_ / 128, (B_ * T_ + 255) / 256), 256, GEMM_SMEM>>>(
        xrh, xrl, wqh, wql, b_qkv, qkvbuf, B_ * T_, QKVW_, D_);

    // 3. windowed attention (tensor cores) -> hi/lo planes
    attn_tc<<<dim3(S_ / 64, H_, B_), 128, ATTN_SMEM>>>(qkvbuf, ath, atl);

    // 4. out = attn @ W_out^T + b_out : M=4096, N=1024, K=1024
    gemm_bf16<<<dim3(D_ / 128, (B_ * S_) / 256), 256, GEMM_SMEM>>>(
        ath, atl, woh, wol, b_out, out, B_ * S_, D_, D_);
}